// round 16
// baseline (speedup 1.0000x reference)
#include <cuda_runtime.h>
#include <cuda_fp16.h>
#include <cstdint>

#define NN 100000
#define NE 3200000
#define NL 200000
#define CAP 128                 // 4 sub-segments x 32 slots per node

// ---------------- scratch (device globals) ----------------------------------
__device__ __align__(16) int    g_deg4[NN * 4]; // 4 sub-counters/node; re-zeroed by k_decode
__device__ float                g_inv[NN];
__device__ __align__(16) int    g_csr[NN * CAP];    // padded, dst-grouped src ids (4 segments)
__device__ __align__(16) float  g_xs[NN * 4];       // x * inv[s]
__device__ __align__(16) __half g_W2Tg[64 * 128];   // fp16 W2 transposed [n][k]
__device__ __align__(16) __half2 g_hW2h[NN * 32];   // fp16, scaled by inv[s]
__device__ __align__(16) __half g_zh[NN * 64];      // fp16 z (decode table)

// ---------------- 1) degree-count + CSR fill, 4-way sub-counters -----------------
__global__ void k_fill(const int* __restrict__ ei) {
    int i = blockIdx.x * blockDim.x + threadIdx.x;   // NE/4 threads (3125 blocks exact)
    int sub = i & 3;                                 // fixed segment per thread
    int4 s4 = reinterpret_cast<const int4*>(ei)[i];
    int4 d4 = reinterpret_cast<const int4*>(ei)[NE / 4 + i];
    int p;
    p = atomicAdd(&g_deg4[d4.x * 4 + sub], 1); g_csr[(d4.x << 7) + (sub << 5) + p] = s4.x;
    p = atomicAdd(&g_deg4[d4.y * 4 + sub], 1); g_csr[(d4.y << 7) + (sub << 5) + p] = s4.y;
    p = atomicAdd(&g_deg4[d4.z * 4 + sub], 1); g_csr[(d4.z << 7) + (sub << 5) + p] = s4.z;
    p = atomicAdd(&g_deg4[d4.w * 4 + sub], 1); g_csr[(d4.w << 7) + (sub << 5) + p] = s4.w;
}

// ---------------- 2) inv + scaled x + W2 fp16 transpose -------------------------
__global__ __launch_bounds__(256) void k_prep(const float* __restrict__ x,
                                              const float* __restrict__ W2) {
    int i = blockIdx.x * 256 + threadIdx.x;
    if (i < 8192) {                                  // one-time W2T convert
        int n = i >> 7, k = i & 127;
        g_W2Tg[i] = __float2half_rn(W2[k * 64 + n]);
    }
    if (i < NN) {
        int4 dv = reinterpret_cast<const int4*>(g_deg4)[i];
        int deg = dv.x + dv.y + dv.z + dv.w;
        float inv = rsqrtf((float)deg + 1.0f);
        g_inv[i] = inv;
        float4 xv = reinterpret_cast<const float4*>(x)[i];
        xv.x *= inv; xv.y *= inv; xv.z *= inv; xv.w *= inv;
        reinterpret_cast<float4*>(g_xs)[i] = xv;
    }
}

// ---------------- 3) fused layer-1 gather + dense HMMA ---------------------------
#define L12_NODES_PER_BLOCK 256

__global__ __launch_bounds__(256, 3) void k_layer12(const float* __restrict__ x,
                                                    const float* __restrict__ W1,
                                                    const float* __restrict__ b1) {
    __shared__ float4 sW1T[128];            // W1T[k] = {W1[0..3][k]}
    __shared__ float  sb1[128];
    __shared__ __half sW2T[64][136];        // padded rows (bank-conflict-free frags)
    __shared__ float4 sAgg[256];            // per-node aggregated input (A rows)
    __shared__ float  sInv[256];

    int tid  = threadIdx.x;
    int lane = tid & 31;
    int w    = tid >> 5;

    if (tid < 128) {
        float4 wv;
        wv.x = W1[0 * 128 + tid]; wv.y = W1[1 * 128 + tid];
        wv.z = W1[2 * 128 + tid]; wv.w = W1[3 * 128 + tid];
        sW1T[tid] = wv;
        sb1[tid]  = b1[tid];
    }
    {
        const uint4* src = reinterpret_cast<const uint4*>(g_W2Tg);
        #pragma unroll
        for (int i = tid; i < 1024; i += 256) {
            int r = i >> 4, cv = i & 15;
            *reinterpret_cast<uint4*>(&sW2T[r][cv * 8]) = src[i];
        }
    }

    // ---- phase 1: gather 256 nodes; 8 lanes/node -> 2 lanes per segment ----
    {
        int c    = tid & 7;
        int sub  = c >> 1;            // segment 0..3
        int half = c & 1;             // 0 or 1 within segment
        #pragma unroll
        for (int pass = 0; pass < 8; pass++) {
            int li   = pass * 32 + (tid >> 3);       // local node index 0..255
            int node = blockIdx.x * L12_NODES_PER_BLOCK + li;
            float4 acc = make_float4(0.f, 0.f, 0.f, 0.f);
            float inv = 0.f;
            if (node < NN) {
                int4 dv = reinterpret_cast<const int4*>(g_deg4)[node];
                int dsub = (sub == 0) ? dv.x : (sub == 1) ? dv.y : (sub == 2) ? dv.z : dv.w;
                int segstart = (node << 7) + (sub << 5);
                inv = g_inv[node];
                for (int j = 4 * half; j < dsub; j += 8) {
                    int4 s = *reinterpret_cast<const int4*>(&g_csr[segstart + j]);
                    {
                        float4 v = reinterpret_cast<const float4*>(g_xs)[s.x];
                        acc.x += v.x; acc.y += v.y; acc.z += v.z; acc.w += v.w;
                    }
                    if (j + 1 < dsub) {
                        float4 v = reinterpret_cast<const float4*>(g_xs)[s.y];
                        acc.x += v.x; acc.y += v.y; acc.z += v.z; acc.w += v.w;
                    }
                    if (j + 2 < dsub) {
                        float4 v = reinterpret_cast<const float4*>(g_xs)[s.z];
                        acc.x += v.x; acc.y += v.y; acc.z += v.z; acc.w += v.w;
                    }
                    if (j + 3 < dsub) {
                        float4 v = reinterpret_cast<const float4*>(g_xs)[s.w];
                        acc.x += v.x; acc.y += v.y; acc.z += v.z; acc.w += v.w;
                    }
                }
            }
            #pragma unroll
            for (int o = 4; o >= 1; o >>= 1) {
                acc.x += __shfl_xor_sync(0xffffffffu, acc.x, o);
                acc.y += __shfl_xor_sync(0xffffffffu, acc.y, o);
                acc.z += __shfl_xor_sync(0xffffffffu, acc.z, o);
                acc.w += __shfl_xor_sync(0xffffffffu, acc.w, o);
            }
            if (c == 0) {
                if (node < NN) {
                    float i2 = inv * inv;
                    float4 xv = reinterpret_cast<const float4*>(x)[node];
                    acc.x = fmaf(xv.x, i2, acc.x * inv);
                    acc.y = fmaf(xv.y, i2, acc.y * inv);
                    acc.z = fmaf(xv.z, i2, acc.z * inv);
                    acc.w = fmaf(xv.w, i2, acc.w * inv);
                }
                sAgg[li] = acc;
                sInv[li] = inv;
            }
        }
    }
    __syncthreads();

    // ---- phase 2: dense HMMA ----
    int g = lane >> 2;          // 0..7 (fragment row group)
    int t = lane & 3;           // 0..3 (fragment column group)

    #pragma unroll
    for (int it = 0; it < 2; it++) {
        int lbase = (it * 8 + w) * 16;
        int base  = blockIdx.x * L12_NODES_PER_BLOCK + lbase;
        int n0 = base + g;
        int n1 = base + g + 8;
        bool v0 = (n0 < NN), v1 = (n1 < NN);

        float4 A0 = sAgg[lbase + g];
        float4 A1 = sAgg[lbase + g + 8];
        float iv0 = sInv[lbase + g];
        float iv1 = sInv[lbase + g + 8];

        float d[8][4];
        #pragma unroll
        for (int nt = 0; nt < 8; nt++) {
            d[nt][0] = 0.f; d[nt][1] = 0.f; d[nt][2] = 0.f; d[nt][3] = 0.f;
        }

        #pragma unroll
        for (int kt = 0; kt < 8; kt++) {
            int c0 = kt * 16 + 2 * t;       // fragment cols c0, c0+1
            int c2 = c0 + 8;                // fragment cols c2, c2+1

            float4 wa = sW1T[c0], wb = sW1T[c0 + 1];
            float4 wc = sW1T[c2], wd = sW1T[c2 + 1];
            float ba = sb1[c0], bb = sb1[c0 + 1], bc = sb1[c2], bd = sb1[c2 + 1];

            float h00 = ba, h01 = bb, h02 = bc, h03 = bd;    // node n0
            h00 = fmaf(A0.x, wa.x, h00); h00 = fmaf(A0.y, wa.y, h00);
            h00 = fmaf(A0.z, wa.z, h00); h00 = fmaf(A0.w, wa.w, h00);
            h01 = fmaf(A0.x, wb.x, h01); h01 = fmaf(A0.y, wb.y, h01);
            h01 = fmaf(A0.z, wb.z, h01); h01 = fmaf(A0.w, wb.w, h01);
            h02 = fmaf(A0.x, wc.x, h02); h02 = fmaf(A0.y, wc.y, h02);
            h02 = fmaf(A0.z, wc.z, h02); h02 = fmaf(A0.w, wc.w, h02);
            h03 = fmaf(A0.x, wd.x, h03); h03 = fmaf(A0.y, wd.y, h03);
            h03 = fmaf(A0.z, wd.z, h03); h03 = fmaf(A0.w, wd.w, h03);

            float h10 = ba, h11 = bb, h12 = bc, h13 = bd;    // node n1
            h10 = fmaf(A1.x, wa.x, h10); h10 = fmaf(A1.y, wa.y, h10);
            h10 = fmaf(A1.z, wa.z, h10); h10 = fmaf(A1.w, wa.w, h10);
            h11 = fmaf(A1.x, wb.x, h11); h11 = fmaf(A1.y, wb.y, h11);
            h11 = fmaf(A1.z, wb.z, h11); h11 = fmaf(A1.w, wb.w, h11);
            h12 = fmaf(A1.x, wc.x, h12); h12 = fmaf(A1.y, wc.y, h12);
            h12 = fmaf(A1.z, wc.z, h12); h12 = fmaf(A1.w, wc.w, h12);
            h13 = fmaf(A1.x, wd.x, h13); h13 = fmaf(A1.y, wd.y, h13);
            h13 = fmaf(A1.z, wd.z, h13); h13 = fmaf(A1.w, wd.w, h13);

            __half2 f0 = __floats2half2_rn(fmaxf(h00, 0.f), fmaxf(h01, 0.f));
            __half2 f1 = __floats2half2_rn(fmaxf(h10, 0.f), fmaxf(h11, 0.f));
            __half2 f2 = __floats2half2_rn(fmaxf(h02, 0.f), fmaxf(h03, 0.f));
            __half2 f3 = __floats2half2_rn(fmaxf(h12, 0.f), fmaxf(h13, 0.f));
            uint32_t a0 = *reinterpret_cast<uint32_t*>(&f0);
            uint32_t a1 = *reinterpret_cast<uint32_t*>(&f1);
            uint32_t a2 = *reinterpret_cast<uint32_t*>(&f2);
            uint32_t a3 = *reinterpret_cast<uint32_t*>(&f3);

            int k0 = kt * 16 + 2 * t;
            #pragma unroll
            for (int nt = 0; nt < 8; nt++) {
                int n = nt * 8 + g;
                uint32_t bb0 = *reinterpret_cast<const uint32_t*>(&sW2T[n][k0]);
                uint32_t bb1 = *reinterpret_cast<const uint32_t*>(&sW2T[n][k0 + 8]);
                asm volatile(
                    "mma.sync.aligned.m16n8k16.row.col.f32.f16.f16.f32 "
                    "{%0,%1,%2,%3}, {%4,%5,%6,%7}, {%8,%9}, {%0,%1,%2,%3};"
                    : "+f"(d[nt][0]), "+f"(d[nt][1]), "+f"(d[nt][2]), "+f"(d[nt][3])
                    : "r"(a0), "r"(a1), "r"(a2), "r"(a3), "r"(bb0), "r"(bb1));
            }
        }

        if (v0) {
            #pragma unroll
            for (int nt = 0; nt < 8; nt++)
                g_hW2h[n0 * 32 + nt * 4 + t] =
                    __floats2half2_rn(d[nt][0] * iv0, d[nt][1] * iv0);
        }
        if (v1) {
            #pragma unroll
            for (int nt = 0; nt < 8; nt++)
                g_hW2h[n1 * 32 + nt * 4 + t] =
                    __floats2half2_rn(d[nt][2] * iv1, d[nt][3] * iv1);
        }
    }
}

// ---------------- 4) layer-2 gather (8 lanes/node, 4 segments) -------------------
__device__ __forceinline__ void add_h8(float* a, const uint4& v) {
    float2 f0 = __half22float2(*reinterpret_cast<const __half2*>(&v.x));
    float2 f1 = __half22float2(*reinterpret_cast<const __half2*>(&v.y));
    float2 f2 = __half22float2(*reinterpret_cast<const __half2*>(&v.z));
    float2 f3 = __half22float2(*reinterpret_cast<const __half2*>(&v.w));
    a[0] += f0.x; a[1] += f0.y; a[2] += f1.x; a[3] += f1.y;
    a[4] += f2.x; a[5] += f2.y; a[6] += f3.x; a[7] += f3.y;
}

__global__ __launch_bounds__(256) void k_gather2z(const float* __restrict__ b2) {
    unsigned t = blockIdx.x * 256u + threadIdx.x;   // NN*8 threads
    int node = t >> 3;
    int c    = t & 7;
    int start = node << 7;
    float inv = g_inv[node];
    int4 dv = reinterpret_cast<const int4*>(g_deg4)[node];

    const uint4* hrows = reinterpret_cast<const uint4*>(g_hW2h);  // 8 uint4 per row

    float acc[8] = {0.f, 0.f, 0.f, 0.f, 0.f, 0.f, 0.f, 0.f};
    add_h8(acc, hrows[node * 8 + c]);       // self term (hW2h already inv-scaled)

    #pragma unroll
    for (int sub = 0; sub < 4; sub++) {
        int dsub = (sub == 0) ? dv.x : (sub == 1) ? dv.y : (sub == 2) ? dv.z : dv.w;
        int segstart = start + (sub << 5);
        int j = 0;
        for (; j + 3 < dsub; j += 4) {
            int4 s = *reinterpret_cast<const int4*>(&g_csr[segstart + j]);
            uint4 v0 = hrows[s.x * 8 + c];
            uint4 v1 = hrows[s.y * 8 + c];
            uint4 v2 = hrows[s.z * 8 + c];
            uint4 v3 = hrows[s.w * 8 + c];
            add_h8(acc, v0); add_h8(acc, v1); add_h8(acc, v2); add_h8(acc, v3);
        }
        for (; j < dsub; j++) {
            int s0 = g_csr[segstart + j];
            uint4 v0 = hrows[s0 * 8 + c];
            add_h8(acc, v0);
        }
    }

    float4 bb0 = reinterpret_cast<const float4*>(b2)[2 * c];
    float4 bb1 = reinterpret_cast<const float4*>(b2)[2 * c + 1];
    float z0 = fmaf(acc[0], inv, bb0.x);
    float z1 = fmaf(acc[1], inv, bb0.y);
    float z2 = fmaf(acc[2], inv, bb0.z);
    float z3 = fmaf(acc[3], inv, bb0.w);
    float z4 = fmaf(acc[4], inv, bb1.x);
    float z5 = fmaf(acc[5], inv, bb1.y);
    float z6 = fmaf(acc[6], inv, bb1.z);
    float z7 = fmaf(acc[7], inv, bb1.w);

    uint4 zo;
    __half2 h0 = __floats2half2_rn(z0, z1);
    __half2 h1 = __floats2half2_rn(z2, z3);
    __half2 h2 = __floats2half2_rn(z4, z5);
    __half2 h3 = __floats2half2_rn(z6, z7);
    zo.x = *reinterpret_cast<unsigned*>(&h0);
    zo.y = *reinterpret_cast<unsigned*>(&h1);
    zo.z = *reinterpret_cast<unsigned*>(&h2);
    zo.w = *reinterpret_cast<unsigned*>(&h3);
    reinterpret_cast<uint4*>(g_zh)[t] = zo;
}

// ---------------- 5) decode (8 lanes/edge, uint4) + re-zero g_deg4 ----------------
__global__ __launch_bounds__(256) void k_decode(const int* __restrict__ eli,
                                                float* __restrict__ out) {
    unsigned t = blockIdx.x * 256u + threadIdx.x;   // NL*8 threads
    int e = t >> 3;
    int c = t & 7;
    int a = eli[e];
    int b = eli[NL + e];
    const uint4* zr = reinterpret_cast<const uint4*>(g_zh);
    uint4 va = zr[a * 8 + c];
    uint4 vb = zr[b * 8 + c];
    float2 a0 = __half22float2(*reinterpret_cast<__half2*>(&va.x));
    float2 a1 = __half22float2(*reinterpret_cast<__half2*>(&va.y));
    float2 a2 = __half22float2(*reinterpret_cast<__half2*>(&va.z));
    float2 a3 = __half22float2(*reinterpret_cast<__half2*>(&va.w));
    float2 b0 = __half22float2(*reinterpret_cast<__half2*>(&vb.x));
    float2 b1 = __half22float2(*reinterpret_cast<__half2*>(&vb.y));
    float2 b2 = __half22float2(*reinterpret_cast<__half2*>(&vb.z));
    float2 b3 = __half22float2(*reinterpret_cast<__half2*>(&vb.w));
    float p = a0.x * b0.x + a0.y * b0.y + a1.x * b1.x + a1.y * b1.y
            + a2.x * b2.x + a2.y * b2.y + a3.x * b3.x + a3.y * b3.y;
    #pragma unroll
    for (int o = 4; o >= 1; o >>= 1) p += __shfl_xor_sync(0xffffffffu, p, o);
    if (c == 0) out[e] = p;
    if (t < 4 * NN) g_deg4[t] = 0;   // restore precondition for the next replay
}

// ---------------- launch ----------------------------------------------------------
extern "C" void kernel_launch(void* const* d_in, const int* in_sizes, int n_in,
                              void* d_out, int out_size) {
    const float* x   = (const float*)d_in[0];
    const int*   ei  = (const int*)  d_in[1];
    const int*   eli = (const int*)  d_in[2];
    const float* W1  = (const float*)d_in[3];
    const float* b1  = (const float*)d_in[4];
    const float* W2  = (const float*)d_in[5];
    const float* b2  = (const float*)d_in[6];
    float* out = (float*)d_out;

    k_fill    <<<NE / 4 / 256, 256>>>(ei);       // 3125 blocks, exact
    k_prep    <<<(NN + 255) / 256, 256>>>(x, W2);
    k_layer12 <<<(NN + L12_NODES_PER_BLOCK - 1) / L12_NODES_PER_BLOCK, 256>>>(x, W1, b1);
    k_gather2z<<<NN * 8 / 256, 256>>>(b2);
    k_decode  <<<NL * 8 / 256, 256>>>(eli, out);
}

// round 17
// speedup vs baseline: 1.2707x; 1.2707x over previous
#include <cuda_runtime.h>
#include <cuda_fp16.h>
#include <cstdint>

#define NN 100000
#define NE 3200000
#define NL 200000
#define CAP 128                 // padded CSR slots per node (mean deg 32, P(>128)~1e-37)

// ---------------- scratch (device globals) ----------------------------------
__device__ int                  g_deg[NN];      // zero-init at load; re-zeroed by k_decode
__device__ float                g_inv[NN];
__device__ __align__(16) int    g_csr[NN * CAP];    // padded, dst-grouped src ids
__device__ __align__(16) float  g_xs[NN * 4];       // x * inv[s]
__device__ __align__(16) __half g_W2Tg[64 * 128];   // fp16 W2 transposed [n][k]
__device__ __align__(16) __half2 g_hW2h[NN * 32];   // fp16, scaled by inv[s]
__device__ __align__(16) __half g_zh[NN * 64];      // fp16 z (decode table)

// ---------------- 1) fused degree-count + CSR fill (4 edges/thread) --------------
__global__ void k_fill(const int* __restrict__ ei) {
    int i = blockIdx.x * blockDim.x + threadIdx.x;   // NE/4 threads (3125 blocks exact)
    int4 s4 = reinterpret_cast<const int4*>(ei)[i];
    int4 d4 = reinterpret_cast<const int4*>(ei)[NE / 4 + i];
    int p;
    p = atomicAdd(&g_deg[d4.x], 1); g_csr[(d4.x << 7) + p] = s4.x;
    p = atomicAdd(&g_deg[d4.y], 1); g_csr[(d4.y << 7) + p] = s4.y;
    p = atomicAdd(&g_deg[d4.z], 1); g_csr[(d4.z << 7) + p] = s4.z;
    p = atomicAdd(&g_deg[d4.w], 1); g_csr[(d4.w << 7) + p] = s4.w;
}

// ---------------- 2) inv + scaled x + W2 fp16 transpose -------------------------
__global__ __launch_bounds__(256) void k_prep(const float* __restrict__ x,
                                              const float* __restrict__ W2) {
    int i = blockIdx.x * 256 + threadIdx.x;
    if (i < 8192) {                                  // one-time W2T convert
        int n = i >> 7, k = i & 127;
        g_W2Tg[i] = __float2half_rn(W2[k * 64 + n]);
    }
    if (i < NN) {
        float inv = rsqrtf((float)g_deg[i] + 1.0f);
        g_inv[i] = inv;
        float4 xv = reinterpret_cast<const float4*>(x)[i];
        xv.x *= inv; xv.y *= inv; xv.z *= inv; xv.w *= inv;
        reinterpret_cast<float4*>(g_xs)[i] = xv;
    }
}

// ---------------- 3) fused layer-1 gather + double-HMMA dense -------------------
// Phase 1: 8 lanes/node gather xs -> smem sAgg (incl. self term), 8 passes.
// Phase 2: GEMM1 (agg@W1+b1, m16n8k8, bias folded via k=4 ones column) feeds
//          GEMM2 (h@W2, m16n8k16) directly in fragment registers.
#define L12_NODES_PER_BLOCK 256

__global__ __launch_bounds__(256, 3) void k_layer12(const float* __restrict__ x,
                                                    const float* __restrict__ W1,
                                                    const float* __restrict__ b1) {
    __shared__ __half sW1h[128 * 8];        // B1[n][k]: k0-3=W1[k][n], k4=b1[n], k5-7=0
    __shared__ __half sW2T[64][136];        // padded rows (bank-conflict-free frags)
    __shared__ float4 sAgg[256];            // per-node aggregated input (A rows)
    __shared__ float  sInv[256];

    int tid  = threadIdx.x;
    int lane = tid & 31;
    int w    = tid >> 5;

    if (tid < 128) {
        int n = tid;
        sW1h[n * 8 + 0] = __float2half_rn(W1[0 * 128 + n]);
        sW1h[n * 8 + 1] = __float2half_rn(W1[1 * 128 + n]);
        sW1h[n * 8 + 2] = __float2half_rn(W1[2 * 128 + n]);
        sW1h[n * 8 + 3] = __float2half_rn(W1[3 * 128 + n]);
        sW1h[n * 8 + 4] = __float2half_rn(b1[n]);
        sW1h[n * 8 + 5] = __ushort_as_half((unsigned short)0);
        sW1h[n * 8 + 6] = __ushort_as_half((unsigned short)0);
        sW1h[n * 8 + 7] = __ushort_as_half((unsigned short)0);
    }
    {
        const uint4* src = reinterpret_cast<const uint4*>(g_W2Tg);
        #pragma unroll
        for (int i = tid; i < 1024; i += 256) {
            int r = i >> 4, cv = i & 15;
            *reinterpret_cast<uint4*>(&sW2T[r][cv * 8]) = src[i];
        }
    }

    // ---- phase 1: gather 256 nodes, 8 lanes per node, 8 passes ----
    {
        int c = tid & 7;
        #pragma unroll
        for (int pass = 0; pass < 8; pass++) {
            int li   = pass * 32 + (tid >> 3);       // local node index 0..255
            int node = blockIdx.x * L12_NODES_PER_BLOCK + li;
            float4 acc = make_float4(0.f, 0.f, 0.f, 0.f);
            float inv = 0.f;
            if (node < NN) {
                int start = node << 7;
                int deg   = g_deg[node];
                inv = g_inv[node];
                for (int j = 4 * c; j < deg; j += 32) {
                    int4 s = *reinterpret_cast<const int4*>(&g_csr[start + j]);
                    {
                        float4 v = reinterpret_cast<const float4*>(g_xs)[s.x];
                        acc.x += v.x; acc.y += v.y; acc.z += v.z; acc.w += v.w;
                    }
                    if (j + 1 < deg) {
                        float4 v = reinterpret_cast<const float4*>(g_xs)[s.y];
                        acc.x += v.x; acc.y += v.y; acc.z += v.z; acc.w += v.w;
                    }
                    if (j + 2 < deg) {
                        float4 v = reinterpret_cast<const float4*>(g_xs)[s.z];
                        acc.x += v.x; acc.y += v.y; acc.z += v.z; acc.w += v.w;
                    }
                    if (j + 3 < deg) {
                        float4 v = reinterpret_cast<const float4*>(g_xs)[s.w];
                        acc.x += v.x; acc.y += v.y; acc.z += v.z; acc.w += v.w;
                    }
                }
            }
            #pragma unroll
            for (int o = 4; o >= 1; o >>= 1) {
                acc.x += __shfl_xor_sync(0xffffffffu, acc.x, o);
                acc.y += __shfl_xor_sync(0xffffffffu, acc.y, o);
                acc.z += __shfl_xor_sync(0xffffffffu, acc.z, o);
                acc.w += __shfl_xor_sync(0xffffffffu, acc.w, o);
            }
            if (c == 0) {
                if (node < NN) {
                    float i2 = inv * inv;
                    float4 xv = reinterpret_cast<const float4*>(x)[node];
                    acc.x = fmaf(xv.x, i2, acc.x * inv);
                    acc.y = fmaf(xv.y, i2, acc.y * inv);
                    acc.z = fmaf(xv.z, i2, acc.z * inv);
                    acc.w = fmaf(xv.w, i2, acc.w * inv);
                }
                sAgg[li] = acc;
                sInv[li] = inv;
            }
        }
    }
    __syncthreads();

    // ---- phase 2: GEMM1 (k8) -> GEMM2 (k16), all on tensor pipe ----
    int g = lane >> 2;          // 0..7 (fragment row group)
    int t = lane & 3;           // 0..3 (fragment column group)

    #pragma unroll
    for (int it = 0; it < 2; it++) {
        int lbase = (it * 8 + w) * 16;
        int base  = blockIdx.x * L12_NODES_PER_BLOCK + lbase;
        int n0 = base + g;
        int n1 = base + g + 8;
        bool v0 = (n0 < NN), v1 = (n1 < NN);

        float4 A0 = sAgg[lbase + g];
        float4 A1 = sAgg[lbase + g + 8];
        float iv0 = sInv[lbase + g];
        float iv1 = sInv[lbase + g + 8];

        // GEMM1 A fragment (k=8: cols 0-3 agg, col 4 = 1.0 bias carrier)
        float p0 = (t == 0) ? A0.x : (t == 1) ? A0.z : (t == 2) ? 1.f : 0.f;
        float p1 = (t == 0) ? A0.y : (t == 1) ? A0.w : 0.f;
        float q0 = (t == 0) ? A1.x : (t == 1) ? A1.z : (t == 2) ? 1.f : 0.f;
        float q1 = (t == 0) ? A1.y : (t == 1) ? A1.w : 0.f;
        __half2 hpa = __floats2half2_rn(p0, p1);
        __half2 hpb = __floats2half2_rn(q0, q1);
        uint32_t g1a0 = *reinterpret_cast<uint32_t*>(&hpa);
        uint32_t g1a1 = *reinterpret_cast<uint32_t*>(&hpb);

        float d[8][4];
        #pragma unroll
        for (int nt = 0; nt < 8; nt++) {
            d[nt][0] = 0.f; d[nt][1] = 0.f; d[nt][2] = 0.f; d[nt][3] = 0.f;
        }

        const float fz = 0.f;

        #pragma unroll
        for (int kt = 0; kt < 8; kt++) {
            // GEMM1 for h columns [16kt, 16kt+16): two k8 n-tiles
            uint32_t w1b0 = *reinterpret_cast<const uint32_t*>(&sW1h[(16 * kt + g) * 8 + 2 * t]);
            uint32_t w1b1 = *reinterpret_cast<const uint32_t*>(&sW1h[(16 * kt + 8 + g) * 8 + 2 * t]);
            float e0, e1, e2, e3, f0, f1, f2, f3;
            asm volatile(
                "mma.sync.aligned.m16n8k8.row.col.f32.f16.f16.f32 "
                "{%0,%1,%2,%3}, {%4,%5}, {%6}, {%7,%8,%9,%10};"
                : "=f"(e0), "=f"(e1), "=f"(e2), "=f"(e3)
                : "r"(g1a0), "r"(g1a1), "r"(w1b0), "f"(fz), "f"(fz), "f"(fz), "f"(fz));
            asm volatile(
                "mma.sync.aligned.m16n8k8.row.col.f32.f16.f16.f32 "
                "{%0,%1,%2,%3}, {%4,%5}, {%6}, {%7,%8,%9,%10};"
                : "=f"(f0), "=f"(f1), "=f"(f2), "=f"(f3)
                : "r"(g1a0), "r"(g1a1), "r"(w1b1), "f"(fz), "f"(fz), "f"(fz), "f"(fz));

            // relu + pack: GEMM1 D frags map exactly onto GEMM2 A frags
            __half2 fa0 = __floats2half2_rn(fmaxf(e0, 0.f), fmaxf(e1, 0.f));
            __half2 fa1 = __floats2half2_rn(fmaxf(e2, 0.f), fmaxf(e3, 0.f));
            __half2 fa2 = __floats2half2_rn(fmaxf(f0, 0.f), fmaxf(f1, 0.f));
            __half2 fa3 = __floats2half2_rn(fmaxf(f2, 0.f), fmaxf(f3, 0.f));
            uint32_t a0 = *reinterpret_cast<uint32_t*>(&fa0);
            uint32_t a1 = *reinterpret_cast<uint32_t*>(&fa1);
            uint32_t a2 = *reinterpret_cast<uint32_t*>(&fa2);
            uint32_t a3 = *reinterpret_cast<uint32_t*>(&fa3);

            int k0 = kt * 16 + 2 * t;
            #pragma unroll
            for (int nt = 0; nt < 8; nt++) {
                int n = nt * 8 + g;
                uint32_t bb0 = *reinterpret_cast<const uint32_t*>(&sW2T[n][k0]);
                uint32_t bb1 = *reinterpret_cast<const uint32_t*>(&sW2T[n][k0 + 8]);
                asm volatile(
                    "mma.sync.aligned.m16n8k16.row.col.f32.f16.f16.f32 "
                    "{%0,%1,%2,%3}, {%4,%5,%6,%7}, {%8,%9}, {%0,%1,%2,%3};"
                    : "+f"(d[nt][0]), "+f"(d[nt][1]), "+f"(d[nt][2]), "+f"(d[nt][3])
                    : "r"(a0), "r"(a1), "r"(a2), "r"(a3), "r"(bb0), "r"(bb1));
            }
        }

        if (v0) {
            #pragma unroll
            for (int nt = 0; nt < 8; nt++)
                g_hW2h[n0 * 32 + nt * 4 + t] =
                    __floats2half2_rn(d[nt][0] * iv0, d[nt][1] * iv0);
        }
        if (v1) {
            #pragma unroll
            for (int nt = 0; nt < 8; nt++)
                g_hW2h[n1 * 32 + nt * 4 + t] =
                    __floats2half2_rn(d[nt][2] * iv1, d[nt][3] * iv1);
        }
    }
}

// ---------------- 4) layer-2 gather (8 lanes/node, uint4 rows, unroll 8) --------
__device__ __forceinline__ void add_h8(float* a, const uint4& v) {
    float2 f0 = __half22float2(*reinterpret_cast<const __half2*>(&v.x));
    float2 f1 = __half22float2(*reinterpret_cast<const __half2*>(&v.y));
    float2 f2 = __half22float2(*reinterpret_cast<const __half2*>(&v.z));
    float2 f3 = __half22float2(*reinterpret_cast<const __half2*>(&v.w));
    a[0] += f0.x; a[1] += f0.y; a[2] += f1.x; a[3] += f1.y;
    a[4] += f2.x; a[5] += f2.y; a[6] += f3.x; a[7] += f3.y;
}

__global__ __launch_bounds__(256) void k_gather2z(const float* __restrict__ b2) {
    unsigned t = blockIdx.x * 256u + threadIdx.x;   // NN*8 threads
    int node = t >> 3;
    int c    = t & 7;
    int start = node << 7;
    int deg   = g_deg[node];
    float inv = g_inv[node];

    const uint4* hrows = reinterpret_cast<const uint4*>(g_hW2h);  // 8 uint4 per row

    float acc[8] = {0.f, 0.f, 0.f, 0.f, 0.f, 0.f, 0.f, 0.f};
    add_h8(acc, hrows[node * 8 + c]);       // self term (hW2h already inv-scaled)

    int j = 0;
    for (; j + 7 < deg; j += 8) {
        int4 sa = *reinterpret_cast<const int4*>(&g_csr[start + j]);
        int4 sb = *reinterpret_cast<const int4*>(&g_csr[start + j + 4]);
        uint4 v0 = hrows[sa.x * 8 + c];
        uint4 v1 = hrows[sa.y * 8 + c];
        uint4 v2 = hrows[sa.z * 8 + c];
        uint4 v3 = hrows[sa.w * 8 + c];
        uint4 v4 = hrows[sb.x * 8 + c];
        uint4 v5 = hrows[sb.y * 8 + c];
        uint4 v6 = hrows[sb.z * 8 + c];
        uint4 v7 = hrows[sb.w * 8 + c];
        add_h8(acc, v0); add_h8(acc, v1); add_h8(acc, v2); add_h8(acc, v3);
        add_h8(acc, v4); add_h8(acc, v5); add_h8(acc, v6); add_h8(acc, v7);
    }
    for (; j + 3 < deg; j += 4) {
        int4 s = *reinterpret_cast<const int4*>(&g_csr[start + j]);
        uint4 v0 = hrows[s.x * 8 + c];
        uint4 v1 = hrows[s.y * 8 + c];
        uint4 v2 = hrows[s.z * 8 + c];
        uint4 v3 = hrows[s.w * 8 + c];
        add_h8(acc, v0); add_h8(acc, v1); add_h8(acc, v2); add_h8(acc, v3);
    }
    for (; j < deg; j++) {
        int s0 = g_csr[start + j];
        uint4 v0 = hrows[s0 * 8 + c];
        add_h8(acc, v0);
    }

    float4 bb0 = reinterpret_cast<const float4*>(b2)[2 * c];
    float4 bb1 = reinterpret_cast<const float4*>(b2)[2 * c + 1];
    float z0 = fmaf(acc[0], inv, bb0.x);
    float z1 = fmaf(acc[1], inv, bb0.y);
    float z2 = fmaf(acc[2], inv, bb0.z);
    float z3 = fmaf(acc[3], inv, bb0.w);
    float z4 = fmaf(acc[4], inv, bb1.x);
    float z5 = fmaf(acc[5], inv, bb1.y);
    float z6 = fmaf(acc[6], inv, bb1.z);
    float z7 = fmaf(acc[7], inv, bb1.w);

    uint4 zo;
    __half2 h0 = __floats2half2_rn(z0, z1);
    __half2 h1 = __floats2half2_rn(z2, z3);
    __half2 h2 = __floats2half2_rn(z4, z5);
    __half2 h3 = __floats2half2_rn(z6, z7);
    zo.x = *reinterpret_cast<unsigned*>(&h0);
    zo.y = *reinterpret_cast<unsigned*>(&h1);
    zo.z = *reinterpret_cast<unsigned*>(&h2);
    zo.w = *reinterpret_cast<unsigned*>(&h3);
    reinterpret_cast<uint4*>(g_zh)[t] = zo;
}

// ---------------- 5) decode (8 lanes/edge, uint4) + re-zero g_deg ---------------
__global__ __launch_bounds__(256) void k_decode(const int* __restrict__ eli,
                                                float* __restrict__ out) {
    unsigned t = blockIdx.x * 256u + threadIdx.x;   // NL*8 threads
    int e = t >> 3;
    int c = t & 7;
    int a = eli[e];
    int b = eli[NL + e];
    const uint4* zr = reinterpret_cast<const uint4*>(g_zh);
    uint4 va = zr[a * 8 + c];
    uint4 vb = zr[b * 8 + c];
    float2 a0 = __half22float2(*reinterpret_cast<__half2*>(&va.x));
    float2 a1 = __half22float2(*reinterpret_cast<__half2*>(&va.y));
    float2 a2 = __half22float2(*reinterpret_cast<__half2*>(&va.z));
    float2 a3 = __half22float2(*reinterpret_cast<__half2*>(&va.w));
    float2 b0 = __half22float2(*reinterpret_cast<__half2*>(&vb.x));
    float2 b1 = __half22float2(*reinterpret_cast<__half2*>(&vb.y));
    float2 b2 = __half22float2(*reinterpret_cast<__half2*>(&vb.z));
    float2 b3 = __half22float2(*reinterpret_cast<__half2*>(&vb.w));
    float p = a0.x * b0.x + a0.y * b0.y + a1.x * b1.x + a1.y * b1.y
            + a2.x * b2.x + a2.y * b2.y + a3.x * b3.x + a3.y * b3.y;
    #pragma unroll
    for (int o = 4; o >= 1; o >>= 1) p += __shfl_xor_sync(0xffffffffu, p, o);
    if (c == 0) out[e] = p;
    if (t < NN) g_deg[t] = 0;     // restore precondition for the next replay
}

// ---------------- launch ----------------------------------------------------------
extern "C" void kernel_launch(void* const* d_in, const int* in_sizes, int n_in,
                              void* d_out, int out_size) {
    const float* x   = (const float*)d_in[0];
    const int*   ei  = (const int*)  d_in[1];
    const int*   eli = (const int*)  d_in[2];
    const float* W1  = (const float*)d_in[3];
    const float* b1  = (const float*)d_in[4];
    const float* W2  = (const float*)d_in[5];
    const float* b2  = (const float*)d_in[6];
    float* out = (float*)d_out;

    k_fill    <<<NE / 4 / 256, 256>>>(ei);       // 3125 blocks, exact
    k_prep    <<<(NN + 255) / 256, 256>>>(x, W2);
    k_layer12 <<<(NN + L12_NODES_PER_BLOCK - 1) / L12_NODES_PER_BLOCK, 256>>>(x, W1, b1);
    k_gather2z<<<NN * 8 / 256, 256>>>(b2);
    k_decode  <<<NL * 8 / 256, 256>>>(eli, out);
}